// round 2
// baseline (speedup 1.0000x reference)
#include <cuda_runtime.h>
#include <cuda_bf16.h>

#define EPS       0.1f
#define NTHREADS  256
#define NEG_LOG2E -1.4426950408889634f

// Degree-4 poly for ln(1+t), t in [0,1]  (Chebyshev-economized Taylor of
// ln((3+z)/2), z=2t-1; max abs err ~2e-4). Constant term B0 hoisted out and
// applied once per row (exactly) instead of per element.
#define PB0 2.012e-4f
#define PB1 0.9952132f
#define PB2 -0.4638212f
#define PB3 0.2162784f
#define PB4 -0.0548696f

typedef unsigned long long u64;

__device__ __forceinline__ float ex2f(float x) {
    float r; asm("ex2.approx.f32 %0, %1;" : "=f"(r) : "f"(x)); return r;
}
__device__ __forceinline__ u64 pk2(float lo, float hi) {
    u64 r; asm("mov.b64 %0, {%1, %2};" : "=l"(r) : "f"(lo), "f"(hi)); return r;
}
__device__ __forceinline__ u64 fma2(u64 a, u64 b, u64 c) {
    u64 d; asm("fma.rn.f32x2 %0, %1, %2, %3;" : "=l"(d) : "l"(a), "l"(b), "l"(c)); return d;
}
__device__ __forceinline__ float2 up2(u64 v) {
    float lo, hi; asm("mov.b64 {%0, %1}, %2;" : "=f"(lo), "=f"(hi) : "l"(v));
    return make_float2(lo, hi);
}

// Exact (intrinsic-precision) log-sigmoid for the ~100 sparse correction terms.
__device__ __forceinline__ float logsig_exact(float x) {
    float e = __expf(-fabsf(x));
    return fminf(x, 0.0f) - __logf(1.0f + e);
}

__global__ __launch_bounds__(NTHREADS) void ls_loss_kernel(
    const float* __restrict__ output,
    const int*   __restrict__ label,
    const int*   __restrict__ test_label,
    float*       __restrict__ out,
    int num_type, int L)
{
    const int b    = blockIdx.x;
    const int tid  = threadIdx.x;
    const int twoL = 2 * L;

    __shared__ int   lab[128];
    __shared__ float warpsum[NTHREADS / 32];

    if (tid < L)         lab[tid] = label[b * L + tid];
    else if (tid < twoL) lab[tid] = test_label[b * L + (tid - L)];
    __syncthreads();

    const float  c0  = EPS / (float)num_type;
    const float* row = output + (size_t)b * (size_t)num_type;

    // packed poly constants (built once, hoisted by compiler)
    const u64 B4p = pk2(PB4, PB4);
    const u64 B3p = pk2(PB3, PB3);
    const u64 B2p = pk2(PB2, PB2);
    const u64 B1p = pk2(PB1, PB1);

    // ---- dense: sum logsig(row[n]) = sum min(x,0) - sum [B0 + t*Q(t)] ----
    float sm0 = 0.0f, sm1 = 0.0f;   // sum of min(x,0) (+ exact tail terms)
    u64 G0 = 0ull, G1 = 0ull;       // packed sums of t*Q(t)

    const int     nvec = num_type >> 2;
    const float4* rowv = (const float4*)row;

    #pragma unroll 4
    for (int i = tid; i < nvec; i += NTHREADS) {
        float4 v = __ldcs(rowv + i);

        float m0 = fabsf(v.x) * NEG_LOG2E;
        float m1 = fabsf(v.y) * NEG_LOG2E;
        float m2 = fabsf(v.z) * NEG_LOG2E;
        float m3 = fabsf(v.w) * NEG_LOG2E;

        float t0 = ex2f(m0);
        float t1 = ex2f(m1);
        float t2 = ex2f(m2);
        float t3 = ex2f(m3);

        sm0 += fminf(v.x, 0.0f) + fminf(v.y, 0.0f);
        sm1 += fminf(v.z, 0.0f) + fminf(v.w, 0.0f);

        u64 ta = pk2(t0, t1);
        u64 tb = pk2(t2, t3);

        u64 p = fma2(ta, B4p, B3p);
        p     = fma2(ta, p,   B2p);
        p     = fma2(ta, p,   B1p);
        G0    = fma2(ta, p,   G0);

        u64 q = fma2(tb, B4p, B3p);
        q     = fma2(tb, q,   B2p);
        q     = fma2(tb, q,   B1p);
        G1    = fma2(tb, q,   G1);
    }
    // scalar tail (exact formula; num_type % 4 == 0 here so normally empty)
    for (int i = (nvec << 2) + tid; i < num_type; i += NTHREADS)
        sm0 += logsig_exact(row[i]);

    float2 g0 = up2(G0), g1 = up2(G1);
    float  gsum = (g0.x + g0.y) + (g1.x + g1.y);
    float  acc  = ((sm0 + sm1) - gsum) * c0;

    // ---- sparse corrections with set semantics (dedup; test overwrites label) ----
    if (tid < twoL) {
        int raw = lab[tid];
        if (raw != 0) {
            int  j = raw - 1;
            bool canon = true;
            if (tid >= L) {
                for (int k = L; k < tid; k++)
                    if (lab[k] == raw) { canon = false; break; }
                if (canon)
                    acc += (2.0f * (1.0f - EPS) - 2.0f * c0) * logsig_exact(row[j]);
            } else {
                for (int k = 0; k < tid; k++)
                    if (lab[k] == raw) { canon = false; break; }
                if (canon)
                    for (int k = L; k < twoL; k++)
                        if (lab[k] == raw) { canon = false; break; }
                if (canon)
                    acc += ((1.0f - EPS) - c0) * logsig_exact(row[j]);
            }
        }
    }

    // ---- block reduction ----
    #pragma unroll
    for (int o = 16; o > 0; o >>= 1)
        acc += __shfl_down_sync(0xffffffffu, acc, o);
    if ((tid & 31) == 0) warpsum[tid >> 5] = acc;
    __syncthreads();

    if (tid < NTHREADS / 32) {
        float v = warpsum[tid];
        #pragma unroll
        for (int o = NTHREADS / 64; o > 0; o >>= 1)
            v += __shfl_down_sync(0xffu, v, o);
        if (tid == 0) {
            // fold back the hoisted poly constant: loss = c0*N_poly*B0 - v
            float corr = c0 * (float)(nvec << 2) * PB0;
            out[b] = corr - v;
        }
    }
}

extern "C" void kernel_launch(void* const* d_in, const int* in_sizes, int n_in,
                              void* d_out, int out_size)
{
    const float* output     = (const float*)d_in[0];
    const int*   label      = (const int*)d_in[1];
    const int*   test_label = (const int*)d_in[2];
    float*       out        = (float*)d_out;

    const int B        = out_size;               // 4096
    const int num_type = in_sizes[0] / B;        // 32000
    const int L        = in_sizes[1] / B;        // 50

    ls_loss_kernel<<<B, NTHREADS>>>(output, label, test_label, out, num_type, L);
}